// round 14
// baseline (speedup 1.0000x reference)
#include <cuda_runtime.h>
#include <cuda_bf16.h>
#include <cstdint>

// ---------------- problem constants ----------------
#define NU 60000
#define NI 30000
#define NN 90000          // NU + NI
#define D  64
#define D3 192            // 3*D
#define MAXE_DIR 1000000
#define KTOT 1408         // 768 + 512 + 128
#define BK   64           // K chunk
#define NCHUNK 22         // 1408 / 64

// ---------------- device scratch ----------------
__device__ __align__(16) float g_X0[NN * D3];
__device__ __align__(16) float g_X1[NN * D3];
__device__ __align__(16) float g_S [NN * D3];
__device__ __align__(16) float g_H [NN * 128];
__device__ __align__(16) __nv_bfloat16 g_Bh[D3 * KTOT];
__device__ __align__(16) __nv_bfloat16 g_Bl[D3 * KTOT];
__device__ __align__(16) __nv_bfloat16 g_Sh[(size_t)NN * D3];
__device__ __align__(16) __nv_bfloat16 g_Sl[(size_t)NN * D3];
__device__ __align__(16) __nv_bfloat16 g_W1h[2 * 128 * 192];  // [which][n][k]
__device__ __align__(16) __nv_bfloat16 g_W1l[2 * 128 * 192];
__device__ float g_bsum[D3];
__device__ int   g_deg[NN];
__device__ float g_rinv[NN];
__device__ int   g_rowptr[NN + 1];
__device__ int   g_cnt[NN];
__device__ int   g_col[MAXE_DIR];
__device__ int   g_is64;

// ---------------- helpers ----------------
__device__ __forceinline__ uint32_t smem_u32(const void* p) {
    uint32_t a;
    asm("{ .reg .u64 t; cvta.to.shared.u64 t, %1; cvt.u32.u64 %0, t; }" : "=r"(a) : "l"(p));
    return a;
}
__device__ __forceinline__ void cp16(uint32_t saddr, const void* g) {
    asm volatile("cp.async.ca.shared.global [%0], [%1], 16;" :: "r"(saddr), "l"(g));
}
__device__ __forceinline__ void st_zero16(uint32_t saddr) {
    asm volatile("st.shared.v4.u32 [%0], {%1,%1,%1,%1};" :: "r"(saddr), "r"(0u));
}
__device__ __forceinline__ void ldm4(uint32_t* r, uint32_t addr) {
    asm volatile("ldmatrix.sync.aligned.m8n8.x4.shared.b16 {%0,%1,%2,%3}, [%4];"
                 : "=r"(r[0]), "=r"(r[1]), "=r"(r[2]), "=r"(r[3]) : "r"(addr));
}
__device__ __forceinline__ void mma16816(float* d, const uint32_t* a, uint32_t b0, uint32_t b1) {
    asm volatile("mma.sync.aligned.m16n8k16.row.col.f32.bf16.bf16.f32 "
                 "{%0,%1,%2,%3}, {%4,%5,%6,%7}, {%8,%9}, {%0,%1,%2,%3};"
                 : "+f"(d[0]), "+f"(d[1]), "+f"(d[2]), "+f"(d[3])
                 : "r"(a[0]), "r"(a[1]), "r"(a[2]), "r"(a[3]), "r"(b0), "r"(b1));
}
__device__ __forceinline__ void split_bf16(float v, __nv_bfloat16& h, __nv_bfloat16& l) {
    h = __float2bfloat16(v);
    l = __float2bfloat16(v - __bfloat162float(h));
}

// ---------------- edge dtype detection (parallel) ----------------
__global__ void detect_kernel(const int* __restrict__ e32) {
    __shared__ int nz;
    if (threadIdx.x == 0) nz = 0;
    __syncthreads();
    int found = 0;
    for (int i = 1 + 2 * threadIdx.x; i < 2001; i += 512)
        if (e32[i] != 0) found = 1;
    if (found) nz = 1;
    __syncthreads();
    if (threadIdx.x == 0) g_is64 = (nz == 0);
}
__device__ __forceinline__ int edge_at(const int* __restrict__ e32, int idx) {
    int v = g_is64 ? e32[2 * idx] : e32[idx];
    return (v < 0) ? 0 : (v >= NN ? NN - 1 : v);
}

// ---------------- graph preprocessing ----------------
__global__ void zero_kernel() {
    int i = blockIdx.x * blockDim.x + threadIdx.x;
    if (i < NN) { g_deg[i] = 0; g_cnt[i] = 0; }
}
__global__ void deg_kernel(const int* __restrict__ e32, int E) {
    int i = blockIdx.x * blockDim.x + threadIdx.x;
    if (i < E) {
        atomicAdd(&g_deg[edge_at(e32, i)], 1);
        atomicAdd(&g_deg[edge_at(e32, E + i)], 1);
    }
}
__global__ void rinv_kernel() {
    int i = blockIdx.x * blockDim.x + threadIdx.x;
    if (i < NN) {
        int d = g_deg[i];
        g_rinv[i] = rsqrtf((float)(d < 1 ? 1 : d));
    }
}
__global__ void scan_kernel() {
    __shared__ int sums[1024];
    int t = threadIdx.x;
    const int CH = 88;
    int start = t * CH;
    int s = 0;
    for (int i = 0; i < CH; i++) {
        int idx = start + i;
        if (idx < NN) s += g_deg[idx];
    }
    sums[t] = s;
    __syncthreads();
    for (int off = 1; off < 1024; off <<= 1) {
        int add = (t >= off) ? sums[t - off] : 0;
        __syncthreads();
        sums[t] += add;
        __syncthreads();
    }
    int run = (t == 0) ? 0 : sums[t - 1];
    for (int i = 0; i < CH; i++) {
        int idx = start + i;
        if (idx < NN) { g_rowptr[idx] = run; run += g_deg[idx]; }
    }
    if (t == 1023) g_rowptr[NN] = sums[1023];
}
__global__ void fill_kernel(const int* __restrict__ e32, int E) {
    int i = blockIdx.x * blockDim.x + threadIdx.x;
    if (i < E) {
        int s = edge_at(e32, i);
        int d = edge_at(e32, E + i);
        int p0 = g_rowptr[s] + atomicAdd(&g_cnt[s], 1);
        g_col[p0] = d;
        int p1 = g_rowptr[d] + atomicAdd(&g_cnt[d], 1);
        g_col[p1] = s;
    }
}

// ---------------- weight conversions (small, one-shot) ----------------
__global__ void convertB(const float* __restrict__ Wt, const float* __restrict__ Wim,
                         const float* __restrict__ Wst) {
    int idx = blockIdx.x * blockDim.x + threadIdx.x;
    if (idx >= D3 * KTOT) return;
    int n = idx / KTOT, k = idx - n * KTOT;
    int b = n >> 6, d = n & 63;
    float v;
    if (k < 768)        v = Wt [((size_t)b * 768 + k) * 64 + d];
    else if (k < 1280)  v = Wim[((size_t)b * 512 + (k - 768)) * 64 + d];
    else                v = Wst[((size_t)b * 128 + (k - 1280)) * 64 + d];
    __nv_bfloat16 h, l;
    split_bf16(v, h, l);
    g_Bh[idx] = h;
    g_Bl[idx] = l;
}
__global__ void convertW1(const float* __restrict__ Wu1, const float* __restrict__ Wi1) {
    int idx = blockIdx.x * blockDim.x + threadIdx.x;
    if (idx >= 2 * 128 * 192) return;
    int which = idx / (128 * 192);
    int r = idx - which * (128 * 192);
    int n = r / 192, k = r - n * 192;
    const float* W = which ? Wi1 : Wu1;
    float v = W[(size_t)k * 128 + n];
    __nv_bfloat16 h, l;
    split_bf16(v, h, l);
    g_W1h[idx] = h;
    g_W1l[idx] = l;
}
__global__ void bias_kernel(const float* __restrict__ bt, const float* __restrict__ bim,
                            const float* __restrict__ bst) {
    int i = threadIdx.x;
    if (i < D3) g_bsum[i] = bt[i] + bim[i] + bst[i];
}

// ---------------- HMMA feat GEMM: tile 128x96, 2 CTAs/SM, reg-convert A ------
// smem/CTA: A bf16 hi/lo double (64KB) + B hi/lo double (48KB) = 112KB
#define SA_HS(st) ((st) * 32768)
#define SA_LS(st) ((st) * 32768 + 16384)
#define SB_BASE 65536
#define SB_HS(st) (SB_BASE + (st) * 24576)
#define SB_LS(st) (SB_BASE + (st) * 24576 + 12288)
#define SM_TOTAL 114688

__device__ __forceinline__ void feat_ldA(float4* av, int c, int mi0, int tid,
                                         const float* xt, const float* xi, const float* xs) {
    const float* Ap; int stride, off;
    if (c < 12)      { Ap = xt; stride = 768; off = c * 64; }
    else if (c < 20) { Ap = xi; stride = 512; off = c * 64 - 768; }
    else             { Ap = xs; stride = 128; off = c * 64 - 1280; }
    #pragma unroll
    for (int j = 0; j < 8; j++) {
        int li = tid + 256 * j;
        int row = li >> 4, unit = li & 15;
        int gr = mi0 + row;
        av[j] = (gr < NI) ? *(const float4*)(Ap + (size_t)gr * stride + off + unit * 4)
                          : make_float4(0.f, 0.f, 0.f, 0.f);
    }
}

__device__ __forceinline__ void feat_cvtA(char* smem, int stage, const float4* av, int tid) {
    #pragma unroll
    for (int j = 0; j < 8; j++) {
        int li = tid + 256 * j;
        int row = li >> 4, unit = li & 15;
        int s = unit >> 1, half = unit & 1;
        uint32_t sw = row * 128 + ((s * 16) ^ ((row & 7) << 4)) + half * 8;
        __nv_bfloat16 h0, l0, h1, l1, h2, l2, h3, l3;
        split_bf16(av[j].x, h0, l0); split_bf16(av[j].y, h1, l1);
        split_bf16(av[j].z, h2, l2); split_bf16(av[j].w, h3, l3);
        __nv_bfloat162 hp[2] = { __nv_bfloat162(h0, h1), __nv_bfloat162(h2, h3) };
        __nv_bfloat162 lp[2] = { __nv_bfloat162(l0, l1), __nv_bfloat162(l2, l3) };
        *(uint2*)(smem + SA_HS(stage) + sw) = *(const uint2*)hp;
        *(uint2*)(smem + SA_LS(stage) + sw) = *(const uint2*)lp;
    }
}

__device__ __forceinline__ void feat_ldB(uint32_t sb, int stage, int c, int tid,
                                         const __nv_bfloat16* Bh, const __nv_bfloat16* Bl) {
    int k0 = c * BK;
    for (int li = tid; li < 768; li += 256) {
        int row = li >> 3, seg = li & 7;
        size_t o = (size_t)row * KTOT + k0 + seg * 8;
        uint32_t sw = row * 128 + ((seg * 16) ^ ((row & 7) << 4));
        cp16(sb + SB_HS(stage) + sw, Bh + o);
        cp16(sb + SB_LS(stage) + sw, Bl + o);
    }
}

__global__ void __launch_bounds__(256, 2)
feat_gemm_mma(const float* __restrict__ xt, const float* __restrict__ xi,
              const float* __restrict__ xs) {
    extern __shared__ char smem[];
    uint32_t sb = smem_u32(smem);
    int tid = threadIdx.x;
    int wid = tid >> 5, lane = tid & 31;
    int wm = wid & 3, wn = wid >> 2;
    int mi0 = (blockIdx.x >> 1) * 128;
    int ntile = blockIdx.x & 1;
    const __nv_bfloat16* Bh = g_Bh + (size_t)(ntile * 96) * KTOT;
    const __nv_bfloat16* Bl = g_Bl + (size_t)(ntile * 96) * KTOT;

    float acc[2][6][4];
    #pragma unroll
    for (int i = 0; i < 2; i++)
        #pragma unroll
        for (int j = 0; j < 6; j++)
            #pragma unroll
            for (int q = 0; q < 4; q++) acc[i][j][q] = 0.f;

    float4 av[8];
    feat_ldA(av, 0, mi0, tid, xt, xi, xs);
    feat_ldB(sb, 0, 0, tid, Bh, Bl);
    asm volatile("cp.async.commit_group;" ::: "memory");

    for (int c = 0; c < NCHUNK; c++) {
        int stage = c & 1;
        feat_cvtA(smem, stage, av, tid);                 // A(c) regs -> smem
        if (c + 1 < NCHUNK)
            feat_ldA(av, c + 1, mi0, tid, xt, xi, xs);   // LDG A(c+1), hidden under MMA
        asm volatile("cp.async.wait_group 0;" ::: "memory");  // B(c) landed
        __syncthreads();                                 // all warps past MMA(c-1)
        if (c + 1 < NCHUNK) {
            feat_ldB(sb, (c + 1) & 1, c + 1, tid, Bh, Bl);
            asm volatile("cp.async.commit_group;" ::: "memory");
        }

        #pragma unroll
        for (int k16 = 0; k16 < 4; k16++) {
            uint32_t ah[2][4], al[2][4];
            #pragma unroll
            for (int mi = 0; mi < 2; mi++) {
                int r = wm * 32 + mi * 16 + (lane & 15);
                int kb = k16 * 32 + ((lane >> 4) << 4);
                uint32_t off = r * 128 + (kb ^ ((r & 7) << 4));
                ldm4(ah[mi], sb + SA_HS(stage) + off);
                ldm4(al[mi], sb + SA_LS(stage) + off);
            }
            #pragma unroll
            for (int nn = 0; nn < 3; nn++) {
                int g = lane >> 3;
                int r = wn * 48 + nn * 16 + ((g & 2) << 2) + (lane & 7);
                int kb = k16 * 32 + ((g & 1) << 4);
                uint32_t off = r * 128 + (kb ^ ((r & 7) << 4));
                uint32_t bh[4], bl[4];
                ldm4(bh, sb + SB_HS(stage) + off);
                ldm4(bl, sb + SB_LS(stage) + off);
                #pragma unroll
                for (int mi = 0; mi < 2; mi++) {
                    mma16816(acc[mi][nn * 2 + 0], ah[mi], bh[0], bh[1]);
                    mma16816(acc[mi][nn * 2 + 1], ah[mi], bh[2], bh[3]);
                    mma16816(acc[mi][nn * 2 + 0], ah[mi], bl[0], bl[1]);
                    mma16816(acc[mi][nn * 2 + 1], ah[mi], bl[2], bl[3]);
                    mma16816(acc[mi][nn * 2 + 0], al[mi], bh[0], bh[1]);
                    mma16816(acc[mi][nn * 2 + 1], al[mi], bh[2], bh[3]);
                }
            }
        }
    }

    #pragma unroll
    for (int mi = 0; mi < 2; mi++) {
        #pragma unroll
        for (int nn = 0; nn < 3; nn++) {
            #pragma unroll
            for (int nf = 0; nf < 2; nf++) {
                float* f = acc[mi][nn * 2 + nf];
                int row = mi0 + wm * 32 + mi * 16 + (lane >> 2);
                int col = ntile * 96 + wn * 48 + nn * 16 + nf * 8 + (lane & 3) * 2;
                #pragma unroll
                for (int h = 0; h < 2; h++) {
                    int rr = row + h * 8;
                    if (rr < NI) {
                        size_t o = (size_t)(NU + rr) * D3 + col;
                        float v0 = f[h * 2 + 0] + g_bsum[col];
                        float v1 = f[h * 2 + 1] + g_bsum[col + 1];
                        g_X0[o] = v0;     g_X0[o + 1] = v1;
                        g_S [o] = v0;     g_S [o + 1] = v1;
                    }
                }
            }
        }
    }
}

// ---------------- users ----------------
__global__ void user_copy(const float* __restrict__ ue) {
    int idx = blockIdx.x * blockDim.x + threadIdx.x;
    if (idx >= NU * 48) return;
    int n = idx / 48;
    int q = idx - n * 48;
    int b = q >> 4;
    int d4 = q & 15;
    float4 v = ((const float4*)ue)[((size_t)b * NU + n) * 16 + d4];
    ((float4*)g_X0)[(size_t)n * 48 + q] = v;
    ((float4*)g_S )[(size_t)n * 48 + q] = v;
}

// ---------------- SpMM: 16 threads/node, 3 float4 each ----------------
__global__ void spmm(int pass) {
    const float4* __restrict__ Xin4  = (const float4*)(pass ? g_X1 : g_X0);
    float4*       __restrict__ Xout4 = (float4*)(pass ? g_X0 : g_X1);
    int node = blockIdx.x * 16 + (threadIdx.x >> 4);
    int t = threadIdx.x & 15;
    int e0 = g_rowptr[node], e1 = g_rowptr[node + 1];
    float4 A0 = make_float4(0.f, 0.f, 0.f, 0.f), A1 = A0, A2 = A0;
    for (int e = e0; e < e1; e++) {
        int d = g_col[e];
        float w = g_rinv[d];
        const float4* xr = Xin4 + (size_t)d * 48;
        float4 v0 = xr[t], v1 = xr[t + 16], v2 = xr[t + 32];
        A0.x += w * v0.x; A0.y += w * v0.y; A0.z += w * v0.z; A0.w += w * v0.w;
        A1.x += w * v1.x; A1.y += w * v1.y; A1.z += w * v1.z; A1.w += w * v1.w;
        A2.x += w * v2.x; A2.y += w * v2.y; A2.z += w * v2.z; A2.w += w * v2.w;
    }
    float rs = g_rinv[node];
    A0.x *= rs; A0.y *= rs; A0.z *= rs; A0.w *= rs;
    A1.x *= rs; A1.y *= rs; A1.z *= rs; A1.w *= rs;
    A2.x *= rs; A2.y *= rs; A2.z *= rs; A2.w *= rs;
    size_t o = (size_t)node * 48 + t;
    Xout4[o] = A0;  Xout4[o + 16] = A1;  Xout4[o + 32] = A2;
    float4* Sf4 = (float4*)g_S;
    float4 s0 = Sf4[o], s1 = Sf4[o + 16], s2 = Sf4[o + 32];
    s0.x += A0.x; s0.y += A0.y; s0.z += A0.z; s0.w += A0.w;
    s1.x += A1.x; s1.y += A1.y; s1.z += A1.z; s1.w += A1.w;
    s2.x += A2.x; s2.y += A2.y; s2.z += A2.z; s2.w += A2.w;
    Sf4[o] = s0;  Sf4[o + 16] = s1;  Sf4[o + 32] = s2;
    if (pass) {
        float4 ss[3] = {s0, s1, s2};
        #pragma unroll
        for (int q = 0; q < 3; q++) {
            __nv_bfloat16 h0, l0, h1, l1, h2, l2, h3, l3;
            split_bf16(ss[q].x, h0, l0); split_bf16(ss[q].y, h1, l1);
            split_bf16(ss[q].z, h2, l2); split_bf16(ss[q].w, h3, l3);
            size_t bo = (size_t)node * D3 + 4 * t + 64 * q;
            *(__nv_bfloat162*)(g_Sh + bo)     = __nv_bfloat162(h0, h1);
            *(__nv_bfloat162*)(g_Sh + bo + 2) = __nv_bfloat162(h2, h3);
            *(__nv_bfloat162*)(g_Sl + bo)     = __nv_bfloat162(l0, l1);
            *(__nv_bfloat162*)(g_Sl + bo + 2) = __nv_bfloat162(l2, l3);
        }
    }
}

// ---------------- HMMA attention hidden GEMM: H = relu((S/3)@W1 + b1) --------
#define HS_SH 0
#define HS_SL 16384
#define HS_WH 32768
#define HS_WL 49152
#define HSTAGE_SZ 65536
#define SM_TOTAL_H (2 * HSTAGE_SZ)

__device__ __forceinline__ void issue_loads_h(uint32_t sb, int stage, int m0, int c, int tid,
                                              int row_base, int nrows,
                                              const __nv_bfloat16* Wh, const __nv_bfloat16* Wl) {
    uint32_t base = sb + stage * HSTAGE_SZ;
    int k0 = c * 64;
    for (int li = tid; li < 1024; li += 256) {
        int row = li >> 3, seg = li & 7;
        uint32_t sw = row * 128 + ((seg * 16) ^ ((row & 7) << 4));
        if (m0 + row < nrows) {
            size_t o = (size_t)(row_base + m0 + row) * D3 + k0 + seg * 8;
            cp16(base + HS_SH + sw, g_Sh + o);
            cp16(base + HS_SL + sw, g_Sl + o);
        } else {
            st_zero16(base + HS_SH + sw);
            st_zero16(base + HS_SL + sw);
        }
    }
    for (int li = tid; li < 1024; li += 256) {
        int row = li >> 3, seg = li & 7;
        size_t o = (size_t)row * D3 + k0 + seg * 8;
        uint32_t sw = row * 128 + ((seg * 16) ^ ((row & 7) << 4));
        cp16(base + HS_WH + sw, Wh + o);
        cp16(base + HS_WL + sw, Wl + o);
    }
}

__global__ void __launch_bounds__(256, 1)
hidden_gemm_mma(const __nv_bfloat16* __restrict__ Wh, const __nv_bfloat16* __restrict__ Wl,
                const float* __restrict__ b1, int row_base, int nrows)
{
    extern __shared__ char smem[];
    uint32_t sb = smem_u32(smem);
    int tid = threadIdx.x;
    int wid = tid >> 5, lane = tid & 31;
    int wm = wid & 3, wn = wid >> 2;
    int m0 = blockIdx.x * 128;

    float acc[2][8][4];
    #pragma unroll
    for (int i = 0; i < 2; i++)
        #pragma unroll
        for (int j = 0; j < 8; j++)
            #pragma unroll
            for (int q = 0; q < 4; q++) acc[i][j][q] = 0.f;

    issue_loads_h(sb, 0, m0, 0, tid, row_base, nrows, Wh, Wl);
    asm volatile("cp.async.commit_group;" ::: "memory");

    for (int c = 0; c < 3; c++) {
        if (c + 1 < 3) {
            issue_loads_h(sb, (c + 1) & 1, m0, c + 1, tid, row_base, nrows, Wh, Wl);
            asm volatile("cp.async.commit_group;" ::: "memory");
            asm volatile("cp.async.wait_group 1;" ::: "memory");
        } else {
            asm volatile("cp.async.wait_group 0;" ::: "memory");
        }
        __syncthreads();

        uint32_t base = sb + (c & 1) * HSTAGE_SZ;
        #pragma unroll
        for (int k16 = 0; k16 < 4; k16++) {
            uint32_t ah[2][4], al[2][4];
            #pragma unroll
            for (int mi = 0; mi < 2; mi++) {
                int r = wm * 32 + mi * 16 + (lane & 15);
                int kb = k16 * 32 + ((lane >> 4) << 4);
                uint32_t off = r * 128 + (kb ^ ((r & 7) << 4));
                ldm4(ah[mi], base + HS_SH + off);
                ldm4(al[mi], base + HS_SL + off);
            }
            #pragma unroll
            for (int nn = 0; nn < 4; nn++) {
                int g = lane >> 3;
                int r = wn * 64 + nn * 16 + ((g & 2) << 2) + (lane & 7);
                int kb = k16 * 32 + ((g & 1) << 4);
                uint32_t off = r * 128 + (kb ^ ((r & 7) << 4));
                uint32_t bh[4], bl[4];
                ldm4(bh, base + HS_WH + off);
                ldm4(bl, base + HS_WL + off);
                #pragma unroll
                for (int mi = 0; mi < 2; mi++) {
                    mma16816(acc[mi][nn * 2 + 0], ah[mi], bh[0], bh[1]);
                    mma16816(acc[mi][nn * 2 + 1], ah[mi], bh[2], bh[3]);
                    mma16816(acc[mi][nn * 2 + 0], ah[mi], bl[0], bl[1]);
                    mma16816(acc[mi][nn * 2 + 1], ah[mi], bl[2], bl[3]);
                    mma16816(acc[mi][nn * 2 + 0], al[mi], bh[0], bh[1]);
                    mma16816(acc[mi][nn * 2 + 1], al[mi], bh[2], bh[3]);
                }
            }
        }
        __syncthreads();
    }

    const float alpha = 1.f / 3.f;
    #pragma unroll
    for (int mi = 0; mi < 2; mi++) {
        #pragma unroll
        for (int nn = 0; nn < 4; nn++) {
            #pragma unroll
            for (int nf = 0; nf < 2; nf++) {
                float* f = acc[mi][nn * 2 + nf];
                int row = m0 + wm * 32 + mi * 16 + (lane >> 2);
                int col = wn * 64 + nn * 16 + nf * 8 + (lane & 3) * 2;
                #pragma unroll
                for (int h = 0; h < 2; h++) {
                    int rr = row + h * 8;
                    if (rr < nrows) {
                        size_t o = (size_t)(row_base + rr) * 128 + col;
                        g_H[o]     = fmaxf(alpha * f[h * 2 + 0] + b1[col], 0.f);
                        g_H[o + 1] = fmaxf(alpha * f[h * 2 + 1] + b1[col + 1], 0.f);
                    }
                }
            }
        }
    }
}

// ---------------- logits + softmax + combine ----------------
__global__ void combine_kernel(const float* __restrict__ Wu2, const float* __restrict__ bu2,
                               const float* __restrict__ Wi2, const float* __restrict__ bi2,
                               float* __restrict__ out)
{
    __shared__ float W2s[2][384];
    int tid = threadIdx.x;
    for (int li = tid; li < 384; li += 256) {
        W2s[0][li] = Wu2[li];
        W2s[1][li] = Wi2[li];
    }
    __syncthreads();
    int warp = tid >> 5, lane = tid & 31;
    int n = blockIdx.x * 8 + warp;
    if (n >= NN) return;
    int sel = (n >= NU) ? 1 : 0;
    const float* b2 = sel ? bi2 : bu2;

    float p0 = 0.f, p1 = 0.f, p2 = 0.f;
    #pragma unroll
    for (int q = 0; q < 4; q++) {
        int j = lane + 32 * q;
        float h = g_H[(size_t)n * 128 + j];
        p0 += h * W2s[sel][j * 3 + 0];
        p1 += h * W2s[sel][j * 3 + 1];
        p2 += h * W2s[sel][j * 3 + 2];
    }
    #pragma unroll
    for (int off = 16; off; off >>= 1) {
        p0 += __shfl_xor_sync(0xffffffff, p0, off);
        p1 += __shfl_xor_sync(0xffffffff, p1, off);
        p2 += __shfl_xor_sync(0xffffffff, p2, off);
    }
    float l0 = p0 + b2[0], l1 = p1 + b2[1], l2 = p2 + b2[2];
    float mx = fmaxf(l0, fmaxf(l1, l2));
    float e0 = __expf(l0 - mx), e1 = __expf(l1 - mx), e2 = __expf(l2 - mx);
    float inv = 1.f / (e0 + e1 + e2);
    float a0 = e0 * inv, a1 = e1 * inv, a2 = e2 * inv;
    const float sc = 1.f / 3.f;
    #pragma unroll
    for (int q = 0; q < 2; q++) {
        int d = lane + 32 * q;
        float u0 = g_S[(size_t)n * D3 + d] * sc;
        float u1 = g_S[(size_t)n * D3 + 64 + d] * sc;
        float u2 = g_S[(size_t)n * D3 + 128 + d] * sc;
        out[(size_t)n * D + d] = a0 * u0 + a1 * u1 + a2 * u2;
    }
}

// ---------------- launch ----------------
extern "C" void kernel_launch(void* const* d_in, const int* in_sizes, int n_in,
                              void* d_out, int out_size)
{
    const float* xt  = (const float*)d_in[0];
    const float* xi  = (const float*)d_in[1];
    const float* xs  = (const float*)d_in[2];
    const float* ue  = (const float*)d_in[3];
    const float* Wt  = (const float*)d_in[4];
    const float* bt  = (const float*)d_in[5];
    const float* Wim = (const float*)d_in[6];
    const float* bim = (const float*)d_in[7];
    const float* Wst = (const float*)d_in[8];
    const float* bst = (const float*)d_in[9];
    const float* Wu1 = (const float*)d_in[10];
    const float* bu1 = (const float*)d_in[11];
    const float* Wu2 = (const float*)d_in[12];
    const float* bu2 = (const float*)d_in[13];
    const float* Wi1 = (const float*)d_in[14];
    const float* bi1 = (const float*)d_in[15];
    const float* Wi2 = (const float*)d_in[16];
    const float* bi2 = (const float*)d_in[17];
    const int*   e32 = (const int*)d_in[18];
    int E = in_sizes[18] / 2;
    float* out = (float*)d_out;

    static int inited = 0;
    static cudaStream_t s2, s3;
    static cudaEvent_t ev_fork, ev_g, ev_u, ev_sp, ev_hi;
    if (!inited) {
        cudaFuncSetAttribute(feat_gemm_mma, cudaFuncAttributeMaxDynamicSharedMemorySize, SM_TOTAL);
        cudaFuncSetAttribute(hidden_gemm_mma, cudaFuncAttributeMaxDynamicSharedMemorySize, SM_TOTAL_H);
        cudaStreamCreateWithFlags(&s2, cudaStreamNonBlocking);
        cudaStreamCreateWithFlags(&s3, cudaStreamNonBlocking);
        cudaEventCreateWithFlags(&ev_fork, cudaEventDisableTiming);
        cudaEventCreateWithFlags(&ev_g,    cudaEventDisableTiming);
        cudaEventCreateWithFlags(&ev_u,    cudaEventDisableTiming);
        cudaEventCreateWithFlags(&ev_sp,   cudaEventDisableTiming);
        cudaEventCreateWithFlags(&ev_hi,   cudaEventDisableTiming);
        inited = 1;
    }

    __nv_bfloat16* W1h;  cudaGetSymbolAddress((void**)&W1h, g_W1h);
    __nv_bfloat16* W1l;  cudaGetSymbolAddress((void**)&W1l, g_W1l);

    // fork for side streams
    cudaEventRecord(ev_fork, 0);
    cudaStreamWaitEvent(s2, ev_fork, 0);
    cudaStreamWaitEvent(s3, ev_fork, 0);

    // ---- default stream: feature GEMM chain (feat_gemm is 4th launch for ncu) ----
    convertB<<<(D3 * KTOT + 255) / 256, 256>>>(Wt, Wim, Wst);            // 1
    convertW1<<<(2 * 128 * 192 + 255) / 256, 256>>>(Wu1, Wi1);           // 2
    bias_kernel<<<1, 256>>>(bt, bim, bst);                               // 3
    feat_gemm_mma<<<((NI + 127) / 128) * 2, 256, SM_TOTAL>>>(xt, xi, xs);// 4

    // ---- stream s3: users (independent of feat chain) ----
    user_copy<<<(NU * 48 + 255) / 256, 256, 0, s3>>>(ue);
    cudaEventRecord(ev_u, s3);

    // ---- stream s2: graph preprocessing ----
    detect_kernel<<<1, 256, 0, s2>>>(e32);
    zero_kernel<<<(NN + 255) / 256, 256, 0, s2>>>();
    deg_kernel<<<(E + 255) / 256, 256, 0, s2>>>(e32, E);
    rinv_kernel<<<(NN + 255) / 256, 256, 0, s2>>>();
    scan_kernel<<<1, 1024, 0, s2>>>();
    fill_kernel<<<(E + 255) / 256, 256, 0, s2>>>(e32, E);
    cudaEventRecord(ev_g, s2);

    // join: spmm needs graph + features + users
    cudaStreamWaitEvent(0, ev_g, 0);
    cudaStreamWaitEvent(0, ev_u, 0);

    // propagation (pass 2 also emits Sh/Sl); 16 threads/node
    spmm<<<NN / 16, 256>>>(0);
    spmm<<<NN / 16, 256>>>(1);
    cudaEventRecord(ev_sp, 0);

    // attention: users on default stream, items concurrently on s3
    cudaStreamWaitEvent(s3, ev_sp, 0);
    hidden_gemm_mma<<<(NU + 127) / 128, 256, SM_TOTAL_H>>>(W1h, W1l, bu1, 0, NU);
    hidden_gemm_mma<<<(NI + 127) / 128, 256, SM_TOTAL_H, s3>>>(W1h + 128 * 192, W1l + 128 * 192, bi1, NU, NI);
    cudaEventRecord(ev_hi, s3);
    cudaStreamWaitEvent(0, ev_hi, 0);

    combine_kernel<<<(NN + 7) / 8, 256>>>(Wu2, bu2, Wi2, bi2, out);
}

// round 15
// speedup vs baseline: 1.3506x; 1.3506x over previous
#include <cuda_runtime.h>
#include <cuda_bf16.h>
#include <cstdint>

// ---------------- problem constants ----------------
#define NU 60000
#define NI 30000
#define NN 90000          // NU + NI
#define D  64
#define D3 192            // 3*D
#define MAXE_DIR 1000000
#define KTOT 1408         // 768 + 512 + 128
#define BK   64           // K chunk
#define NCHUNK 22         // 1408 / 64

// ---------------- device scratch ----------------
__device__ __align__(16) float g_X0[NN * D3];
__device__ __align__(16) float g_X1[NN * D3];
__device__ __align__(16) float g_S [NN * D3];
__device__ __align__(16) float g_H [NN * 128];
__device__ __align__(16) __nv_bfloat16 g_Bh[D3 * KTOT];
__device__ __align__(16) __nv_bfloat16 g_Bl[D3 * KTOT];
__device__ __align__(16) __nv_bfloat16 g_Sh[(size_t)NN * D3];
__device__ __align__(16) __nv_bfloat16 g_Sl[(size_t)NN * D3];
__device__ __align__(16) __nv_bfloat16 g_W1h[2 * 128 * 192];  // [which][n][k]
__device__ __align__(16) __nv_bfloat16 g_W1l[2 * 128 * 192];
__device__ float g_bsum[D3];
__device__ int   g_deg[NN];
__device__ float g_rinv[NN];
__device__ int   g_rowptr[NN + 1];
__device__ int   g_cnt[NN];
__device__ int   g_col[MAXE_DIR];
__device__ int   g_is64;

// ---------------- helpers ----------------
__device__ __forceinline__ uint32_t smem_u32(const void* p) {
    uint32_t a;
    asm("{ .reg .u64 t; cvta.to.shared.u64 t, %1; cvt.u32.u64 %0, t; }" : "=r"(a) : "l"(p));
    return a;
}
__device__ __forceinline__ void cp16(uint32_t saddr, const void* g) {
    asm volatile("cp.async.ca.shared.global [%0], [%1], 16;" :: "r"(saddr), "l"(g));
}
__device__ __forceinline__ void st_zero16(uint32_t saddr) {
    asm volatile("st.shared.v4.u32 [%0], {%1,%1,%1,%1};" :: "r"(saddr), "r"(0u));
}
__device__ __forceinline__ void ldm4(uint32_t* r, uint32_t addr) {
    asm volatile("ldmatrix.sync.aligned.m8n8.x4.shared.b16 {%0,%1,%2,%3}, [%4];"
                 : "=r"(r[0]), "=r"(r[1]), "=r"(r[2]), "=r"(r[3]) : "r"(addr));
}
__device__ __forceinline__ void mma16816(float* d, const uint32_t* a, uint32_t b0, uint32_t b1) {
    asm volatile("mma.sync.aligned.m16n8k16.row.col.f32.bf16.bf16.f32 "
                 "{%0,%1,%2,%3}, {%4,%5,%6,%7}, {%8,%9}, {%0,%1,%2,%3};"
                 : "+f"(d[0]), "+f"(d[1]), "+f"(d[2]), "+f"(d[3])
                 : "r"(a[0]), "r"(a[1]), "r"(a[2]), "r"(a[3]), "r"(b0), "r"(b1));
}
__device__ __forceinline__ void split_bf16(float v, __nv_bfloat16& h, __nv_bfloat16& l) {
    h = __float2bfloat16(v);
    l = __float2bfloat16(v - __bfloat162float(h));
}

// ---------------- edge dtype detection (parallel) ----------------
__global__ void detect_kernel(const int* __restrict__ e32) {
    __shared__ int nz;
    if (threadIdx.x == 0) nz = 0;
    __syncthreads();
    int found = 0;
    for (int i = 1 + 2 * threadIdx.x; i < 2001; i += 512)
        if (e32[i] != 0) found = 1;
    if (found) nz = 1;
    __syncthreads();
    if (threadIdx.x == 0) g_is64 = (nz == 0);
}
__device__ __forceinline__ int edge_at(const int* __restrict__ e32, int idx) {
    int v = g_is64 ? e32[2 * idx] : e32[idx];
    return (v < 0) ? 0 : (v >= NN ? NN - 1 : v);
}

// ---------------- graph preprocessing ----------------
__global__ void zero_kernel() {
    int i = blockIdx.x * blockDim.x + threadIdx.x;
    if (i < NN) { g_deg[i] = 0; g_cnt[i] = 0; }
}
__global__ void deg_kernel(const int* __restrict__ e32, int E) {
    int i = blockIdx.x * blockDim.x + threadIdx.x;
    if (i < E) {
        atomicAdd(&g_deg[edge_at(e32, i)], 1);
        atomicAdd(&g_deg[edge_at(e32, E + i)], 1);
    }
}
__global__ void rinv_kernel() {
    int i = blockIdx.x * blockDim.x + threadIdx.x;
    if (i < NN) {
        int d = g_deg[i];
        g_rinv[i] = rsqrtf((float)(d < 1 ? 1 : d));
    }
}
__global__ void scan_kernel() {
    __shared__ int sums[1024];
    int t = threadIdx.x;
    const int CH = 88;
    int start = t * CH;
    int s = 0;
    for (int i = 0; i < CH; i++) {
        int idx = start + i;
        if (idx < NN) s += g_deg[idx];
    }
    sums[t] = s;
    __syncthreads();
    for (int off = 1; off < 1024; off <<= 1) {
        int add = (t >= off) ? sums[t - off] : 0;
        __syncthreads();
        sums[t] += add;
        __syncthreads();
    }
    int run = (t == 0) ? 0 : sums[t - 1];
    for (int i = 0; i < CH; i++) {
        int idx = start + i;
        if (idx < NN) { g_rowptr[idx] = run; run += g_deg[idx]; }
    }
    if (t == 1023) g_rowptr[NN] = sums[1023];
}
__global__ void fill_kernel(const int* __restrict__ e32, int E) {
    int i = blockIdx.x * blockDim.x + threadIdx.x;
    if (i < E) {
        int s = edge_at(e32, i);
        int d = edge_at(e32, E + i);
        int p0 = g_rowptr[s] + atomicAdd(&g_cnt[s], 1);
        g_col[p0] = d;
        int p1 = g_rowptr[d] + atomicAdd(&g_cnt[d], 1);
        g_col[p1] = s;
    }
}

// ---------------- weight conversions (small, one-shot) ----------------
__global__ void convertB(const float* __restrict__ Wt, const float* __restrict__ Wim,
                         const float* __restrict__ Wst) {
    int idx = blockIdx.x * blockDim.x + threadIdx.x;
    if (idx >= D3 * KTOT) return;
    int n = idx / KTOT, k = idx - n * KTOT;
    int b = n >> 6, d = n & 63;
    float v;
    if (k < 768)        v = Wt [((size_t)b * 768 + k) * 64 + d];
    else if (k < 1280)  v = Wim[((size_t)b * 512 + (k - 768)) * 64 + d];
    else                v = Wst[((size_t)b * 128 + (k - 1280)) * 64 + d];
    __nv_bfloat16 h, l;
    split_bf16(v, h, l);
    g_Bh[idx] = h;
    g_Bl[idx] = l;
}
__global__ void convertW1(const float* __restrict__ Wu1, const float* __restrict__ Wi1) {
    int idx = blockIdx.x * blockDim.x + threadIdx.x;
    if (idx >= 2 * 128 * 192) return;
    int which = idx / (128 * 192);
    int r = idx - which * (128 * 192);
    int n = r / 192, k = r - n * 192;
    const float* W = which ? Wi1 : Wu1;
    float v = W[(size_t)k * 128 + n];
    __nv_bfloat16 h, l;
    split_bf16(v, h, l);
    g_W1h[idx] = h;
    g_W1l[idx] = l;
}
__global__ void bias_kernel(const float* __restrict__ bt, const float* __restrict__ bim,
                            const float* __restrict__ bst) {
    int i = threadIdx.x;
    if (i < D3) g_bsum[i] = bt[i] + bim[i] + bst[i];
}

// ---------------- HMMA feat GEMM (fused fp32->bf16 split): X0_item = A@B^T + b
#define FAF0 0
#define FAF1 32768
#define FAH  65536
#define FAL  81920
#define FB0  98304
#define FB1  147456
#define FBH  0
#define FBL  24576
#define SM_TOTAL 196608     // 192 KB

__device__ __forceinline__ void feat_issue(uint32_t sb, int stage, int mi0, int c, int tid,
                                           const float* xt, const float* xi, const float* xs) {
    const float* Ap; int stride, off;
    if (c < 12)      { Ap = xt; stride = 768; off = c * 64; }
    else if (c < 20) { Ap = xi; stride = 512; off = c * 64 - 768; }
    else             { Ap = xs; stride = 128; off = c * 64 - 1280; }
    uint32_t abase = sb + (stage ? FAF1 : FAF0);
    for (int li = tid; li < 2048; li += 256) {
        int row = li >> 4, j = li & 15;
        int gr = mi0 + row;
        uint32_t dst = abase + row * 256 + j * 16;
        if (gr < NI) cp16(dst, Ap + (size_t)gr * stride + off + j * 4);
        else         st_zero16(dst);
    }
    uint32_t bbase = sb + (stage ? FB1 : FB0);
    int k0 = c * BK;
    for (int li = tid; li < 1536; li += 256) {
        int row = li >> 3, seg = li & 7;
        size_t o = (size_t)row * KTOT + k0 + seg * 8;
        uint32_t sw = row * 128 + ((seg * 16) ^ ((row & 7) << 4));
        cp16(bbase + FBH + sw, g_Bh + o);
        cp16(bbase + FBL + sw, g_Bl + o);
    }
}

__global__ void __launch_bounds__(256, 1)
feat_gemm_mma(const float* __restrict__ xt, const float* __restrict__ xi,
              const float* __restrict__ xs) {
    extern __shared__ char smem[];
    uint32_t sb = smem_u32(smem);
    int tid = threadIdx.x;
    int wid = tid >> 5, lane = tid & 31;
    int wm = wid & 3, wn = wid >> 2;
    int mi0 = blockIdx.x * 128;

    float acc[2][12][4];
    #pragma unroll
    for (int i = 0; i < 2; i++)
        #pragma unroll
        for (int j = 0; j < 12; j++)
            #pragma unroll
            for (int q = 0; q < 4; q++) acc[i][j][q] = 0.f;

    feat_issue(sb, 0, mi0, 0, tid, xt, xi, xs);
    asm volatile("cp.async.commit_group;" ::: "memory");

    for (int c = 0; c < NCHUNK; c++) {
        if (c + 1 < NCHUNK) {
            feat_issue(sb, (c + 1) & 1, mi0, c + 1, tid, xt, xi, xs);
            asm volatile("cp.async.commit_group;" ::: "memory");
            asm volatile("cp.async.wait_group 1;" ::: "memory");
        } else {
            asm volatile("cp.async.wait_group 0;" ::: "memory");
        }
        __syncthreads();

        // convert fp32 A -> swizzled bf16 hi/lo (single buffer)
        {
            uint32_t abase = sb + ((c & 1) ? FAF1 : FAF0);
            const char* sp = smem + (abase - sb);
            for (int li = tid; li < 1024; li += 256) {
                int row = li >> 3, seg = li & 7;
                const float4* f4 = (const float4*)(sp + row * 256 + seg * 32);
                float4 v0 = f4[0], v1 = f4[1];
                __nv_bfloat16 h[8], l[8];
                split_bf16(v0.x, h[0], l[0]); split_bf16(v0.y, h[1], l[1]);
                split_bf16(v0.z, h[2], l[2]); split_bf16(v0.w, h[3], l[3]);
                split_bf16(v1.x, h[4], l[4]); split_bf16(v1.y, h[5], l[5]);
                split_bf16(v1.z, h[6], l[6]); split_bf16(v1.w, h[7], l[7]);
                uint32_t sw = row * 128 + ((seg * 16) ^ ((row & 7) << 4));
                *(uint4*)(smem + (FAH + sw)) = *(const uint4*)h;
                *(uint4*)(smem + (FAL + sw)) = *(const uint4*)l;
            }
        }
        __syncthreads();

        uint32_t bbase = sb + ((c & 1) ? FB1 : FB0);
        #pragma unroll
        for (int k16 = 0; k16 < 4; k16++) {
            uint32_t ah[2][4], al[2][4];
            #pragma unroll
            for (int mi = 0; mi < 2; mi++) {
                int r = wm * 32 + mi * 16 + (lane & 15);
                int kb = k16 * 32 + ((lane >> 4) << 4);
                uint32_t off = r * 128 + (kb ^ ((r & 7) << 4));
                ldm4(ah[mi], sb + FAH + off);
                ldm4(al[mi], sb + FAL + off);
            }
            #pragma unroll
            for (int nn = 0; nn < 6; nn++) {
                int g = lane >> 3;
                int r = wn * 96 + nn * 16 + ((g & 2) << 2) + (lane & 7);
                int kb = k16 * 32 + ((g & 1) << 4);
                uint32_t off = r * 128 + (kb ^ ((r & 7) << 4));
                uint32_t bh[4], bl[4];
                ldm4(bh, bbase + FBH + off);
                ldm4(bl, bbase + FBL + off);
                #pragma unroll
                for (int mi = 0; mi < 2; mi++) {
                    mma16816(acc[mi][nn * 2 + 0], ah[mi], bh[0], bh[1]);
                    mma16816(acc[mi][nn * 2 + 1], ah[mi], bh[2], bh[3]);
                    mma16816(acc[mi][nn * 2 + 0], ah[mi], bl[0], bl[1]);
                    mma16816(acc[mi][nn * 2 + 1], ah[mi], bl[2], bl[3]);
                    mma16816(acc[mi][nn * 2 + 0], al[mi], bh[0], bh[1]);
                    mma16816(acc[mi][nn * 2 + 1], al[mi], bh[2], bh[3]);
                }
            }
        }
        __syncthreads();
    }

    #pragma unroll
    for (int mi = 0; mi < 2; mi++) {
        #pragma unroll
        for (int nn = 0; nn < 6; nn++) {
            #pragma unroll
            for (int nf = 0; nf < 2; nf++) {
                float* f = acc[mi][nn * 2 + nf];
                int row = mi0 + wm * 32 + mi * 16 + (lane >> 2);
                int col = wn * 96 + nn * 16 + nf * 8 + (lane & 3) * 2;
                #pragma unroll
                for (int h = 0; h < 2; h++) {
                    int rr = row + h * 8;
                    if (rr < NI) {
                        size_t o = (size_t)(NU + rr) * D3 + col;
                        float v0 = f[h * 2 + 0] + g_bsum[col];
                        float v1 = f[h * 2 + 1] + g_bsum[col + 1];
                        g_X0[o] = v0;     g_X0[o + 1] = v1;
                        g_S [o] = v0;     g_S [o + 1] = v1;
                    }
                }
            }
        }
    }
}

// ---------------- users ----------------
__global__ void user_copy(const float* __restrict__ ue) {
    int idx = blockIdx.x * blockDim.x + threadIdx.x;
    if (idx >= NU * 48) return;
    int n = idx / 48;
    int q = idx - n * 48;
    int b = q >> 4;
    int d4 = q & 15;
    float4 v = ((const float4*)ue)[((size_t)b * NU + n) * 16 + d4];
    ((float4*)g_X0)[(size_t)n * 48 + q] = v;
    ((float4*)g_S )[(size_t)n * 48 + q] = v;
}

// ---------------- SpMM: 16 threads/node, 3 float4 each ----------------
__global__ void spmm(int pass) {
    const float4* __restrict__ Xin4  = (const float4*)(pass ? g_X1 : g_X0);
    float4*       __restrict__ Xout4 = (float4*)(pass ? g_X0 : g_X1);
    int node = blockIdx.x * 16 + (threadIdx.x >> 4);
    int t = threadIdx.x & 15;
    int e0 = g_rowptr[node], e1 = g_rowptr[node + 1];
    float4 A0 = make_float4(0.f, 0.f, 0.f, 0.f), A1 = A0, A2 = A0;
    for (int e = e0; e < e1; e++) {
        int d = g_col[e];
        float w = g_rinv[d];
        const float4* xr = Xin4 + (size_t)d * 48;
        float4 v0 = xr[t], v1 = xr[t + 16], v2 = xr[t + 32];
        A0.x += w * v0.x; A0.y += w * v0.y; A0.z += w * v0.z; A0.w += w * v0.w;
        A1.x += w * v1.x; A1.y += w * v1.y; A1.z += w * v1.z; A1.w += w * v1.w;
        A2.x += w * v2.x; A2.y += w * v2.y; A2.z += w * v2.z; A2.w += w * v2.w;
    }
    float rs = g_rinv[node];
    A0.x *= rs; A0.y *= rs; A0.z *= rs; A0.w *= rs;
    A1.x *= rs; A1.y *= rs; A1.z *= rs; A1.w *= rs;
    A2.x *= rs; A2.y *= rs; A2.z *= rs; A2.w *= rs;
    size_t o = (size_t)node * 48 + t;
    Xout4[o] = A0;  Xout4[o + 16] = A1;  Xout4[o + 32] = A2;
    float4* Sf4 = (float4*)g_S;
    float4 s0 = Sf4[o], s1 = Sf4[o + 16], s2 = Sf4[o + 32];
    s0.x += A0.x; s0.y += A0.y; s0.z += A0.z; s0.w += A0.w;
    s1.x += A1.x; s1.y += A1.y; s1.z += A1.z; s1.w += A1.w;
    s2.x += A2.x; s2.y += A2.y; s2.z += A2.z; s2.w += A2.w;
    Sf4[o] = s0;  Sf4[o + 16] = s1;  Sf4[o + 32] = s2;
    if (pass) {
        float4 ss[3] = {s0, s1, s2};
        #pragma unroll
        for (int q = 0; q < 3; q++) {
            __nv_bfloat16 h0, l0, h1, l1, h2, l2, h3, l3;
            split_bf16(ss[q].x, h0, l0); split_bf16(ss[q].y, h1, l1);
            split_bf16(ss[q].z, h2, l2); split_bf16(ss[q].w, h3, l3);
            size_t bo = (size_t)node * D3 + 4 * t + 64 * q;
            *(__nv_bfloat162*)(g_Sh + bo)     = __nv_bfloat162(h0, h1);
            *(__nv_bfloat162*)(g_Sh + bo + 2) = __nv_bfloat162(h2, h3);
            *(__nv_bfloat162*)(g_Sl + bo)     = __nv_bfloat162(l0, l1);
            *(__nv_bfloat162*)(g_Sl + bo + 2) = __nv_bfloat162(l2, l3);
        }
    }
}

// ---------------- HMMA attention hidden GEMM: H = relu((S/3)@W1 + b1) --------
#define HS_SH 0
#define HS_SL 16384
#define HS_WH 32768
#define HS_WL 49152
#define HSTAGE_SZ 65536
#define SM_TOTAL_H (2 * HSTAGE_SZ)

__device__ __forceinline__ void issue_loads_h(uint32_t sb, int stage, int m0, int c, int tid,
                                              int row_base, int nrows,
                                              const __nv_bfloat16* Wh, const __nv_bfloat16* Wl) {
    uint32_t base = sb + stage * HSTAGE_SZ;
    int k0 = c * 64;
    for (int li = tid; li < 1024; li += 256) {
        int row = li >> 3, seg = li & 7;
        uint32_t sw = row * 128 + ((seg * 16) ^ ((row & 7) << 4));
        if (m0 + row < nrows) {
            size_t o = (size_t)(row_base + m0 + row) * D3 + k0 + seg * 8;
            cp16(base + HS_SH + sw, g_Sh + o);
            cp16(base + HS_SL + sw, g_Sl + o);
        } else {
            st_zero16(base + HS_SH + sw);
            st_zero16(base + HS_SL + sw);
        }
    }
    for (int li = tid; li < 1024; li += 256) {
        int row = li >> 3, seg = li & 7;
        size_t o = (size_t)row * D3 + k0 + seg * 8;
        uint32_t sw = row * 128 + ((seg * 16) ^ ((row & 7) << 4));
        cp16(base + HS_WH + sw, Wh + o);
        cp16(base + HS_WL + sw, Wl + o);
    }
}

__global__ void __launch_bounds__(256, 1)
hidden_gemm_mma(const __nv_bfloat16* __restrict__ Wh, const __nv_bfloat16* __restrict__ Wl,
                const float* __restrict__ b1, int row_base, int nrows)
{
    extern __shared__ char smem[];
    uint32_t sb = smem_u32(smem);
    int tid = threadIdx.x;
    int wid = tid >> 5, lane = tid & 31;
    int wm = wid & 3, wn = wid >> 2;
    int m0 = blockIdx.x * 128;

    float acc[2][8][4];
    #pragma unroll
    for (int i = 0; i < 2; i++)
        #pragma unroll
        for (int j = 0; j < 8; j++)
            #pragma unroll
            for (int q = 0; q < 4; q++) acc[i][j][q] = 0.f;

    issue_loads_h(sb, 0, m0, 0, tid, row_base, nrows, Wh, Wl);
    asm volatile("cp.async.commit_group;" ::: "memory");

    for (int c = 0; c < 3; c++) {
        if (c + 1 < 3) {
            issue_loads_h(sb, (c + 1) & 1, m0, c + 1, tid, row_base, nrows, Wh, Wl);
            asm volatile("cp.async.commit_group;" ::: "memory");
            asm volatile("cp.async.wait_group 1;" ::: "memory");
        } else {
            asm volatile("cp.async.wait_group 0;" ::: "memory");
        }
        __syncthreads();

        uint32_t base = sb + (c & 1) * HSTAGE_SZ;
        #pragma unroll
        for (int k16 = 0; k16 < 4; k16++) {
            uint32_t ah[2][4], al[2][4];
            #pragma unroll
            for (int mi = 0; mi < 2; mi++) {
                int r = wm * 32 + mi * 16 + (lane & 15);
                int kb = k16 * 32 + ((lane >> 4) << 4);
                uint32_t off = r * 128 + (kb ^ ((r & 7) << 4));
                ldm4(ah[mi], base + HS_SH + off);
                ldm4(al[mi], base + HS_SL + off);
            }
            #pragma unroll
            for (int nn = 0; nn < 4; nn++) {
                int g = lane >> 3;
                int r = wn * 64 + nn * 16 + ((g & 2) << 2) + (lane & 7);
                int kb = k16 * 32 + ((g & 1) << 4);
                uint32_t off = r * 128 + (kb ^ ((r & 7) << 4));
                uint32_t bh[4], bl[4];
                ldm4(bh, base + HS_WH + off);
                ldm4(bl, base + HS_WL + off);
                #pragma unroll
                for (int mi = 0; mi < 2; mi++) {
                    mma16816(acc[mi][nn * 2 + 0], ah[mi], bh[0], bh[1]);
                    mma16816(acc[mi][nn * 2 + 1], ah[mi], bh[2], bh[3]);
                    mma16816(acc[mi][nn * 2 + 0], ah[mi], bl[0], bl[1]);
                    mma16816(acc[mi][nn * 2 + 1], ah[mi], bl[2], bl[3]);
                    mma16816(acc[mi][nn * 2 + 0], al[mi], bh[0], bh[1]);
                    mma16816(acc[mi][nn * 2 + 1], al[mi], bh[2], bh[3]);
                }
            }
        }
        __syncthreads();
    }

    const float alpha = 1.f / 3.f;
    #pragma unroll
    for (int mi = 0; mi < 2; mi++) {
        #pragma unroll
        for (int nn = 0; nn < 4; nn++) {
            #pragma unroll
            for (int nf = 0; nf < 2; nf++) {
                float* f = acc[mi][nn * 2 + nf];
                int row = m0 + wm * 32 + mi * 16 + (lane >> 2);
                int col = wn * 64 + nn * 16 + nf * 8 + (lane & 3) * 2;
                #pragma unroll
                for (int h = 0; h < 2; h++) {
                    int rr = row + h * 8;
                    if (rr < nrows) {
                        size_t o = (size_t)(row_base + rr) * 128 + col;
                        g_H[o]     = fmaxf(alpha * f[h * 2 + 0] + b1[col], 0.f);
                        g_H[o + 1] = fmaxf(alpha * f[h * 2 + 1] + b1[col + 1], 0.f);
                    }
                }
            }
        }
    }
}

// ---------------- logits + softmax + combine ----------------
__global__ void combine_kernel(const float* __restrict__ Wu2, const float* __restrict__ bu2,
                               const float* __restrict__ Wi2, const float* __restrict__ bi2,
                               float* __restrict__ out)
{
    __shared__ float W2s[2][384];
    int tid = threadIdx.x;
    for (int li = tid; li < 384; li += 256) {
        W2s[0][li] = Wu2[li];
        W2s[1][li] = Wi2[li];
    }
    __syncthreads();
    int warp = tid >> 5, lane = tid & 31;
    int n = blockIdx.x * 8 + warp;
    if (n >= NN) return;
    int sel = (n >= NU) ? 1 : 0;
    const float* b2 = sel ? bi2 : bu2;

    float p0 = 0.f, p1 = 0.f, p2 = 0.f;
    #pragma unroll
    for (int q = 0; q < 4; q++) {
        int j = lane + 32 * q;
        float h = g_H[(size_t)n * 128 + j];
        p0 += h * W2s[sel][j * 3 + 0];
        p1 += h * W2s[sel][j * 3 + 1];
        p2 += h * W2s[sel][j * 3 + 2];
    }
    #pragma unroll
    for (int off = 16; off; off >>= 1) {
        p0 += __shfl_xor_sync(0xffffffff, p0, off);
        p1 += __shfl_xor_sync(0xffffffff, p1, off);
        p2 += __shfl_xor_sync(0xffffffff, p2, off);
    }
    float l0 = p0 + b2[0], l1 = p1 + b2[1], l2 = p2 + b2[2];
    float mx = fmaxf(l0, fmaxf(l1, l2));
    float e0 = __expf(l0 - mx), e1 = __expf(l1 - mx), e2 = __expf(l2 - mx);
    float inv = 1.f / (e0 + e1 + e2);
    float a0 = e0 * inv, a1 = e1 * inv, a2 = e2 * inv;
    const float sc = 1.f / 3.f;
    #pragma unroll
    for (int q = 0; q < 2; q++) {
        int d = lane + 32 * q;
        float u0 = g_S[(size_t)n * D3 + d] * sc;
        float u1 = g_S[(size_t)n * D3 + 64 + d] * sc;
        float u2 = g_S[(size_t)n * D3 + 128 + d] * sc;
        out[(size_t)n * D + d] = a0 * u0 + a1 * u1 + a2 * u2;
    }
}

// ---------------- launch ----------------
extern "C" void kernel_launch(void* const* d_in, const int* in_sizes, int n_in,
                              void* d_out, int out_size)
{
    const float* xt  = (const float*)d_in[0];
    const float* xi  = (const float*)d_in[1];
    const float* xs  = (const float*)d_in[2];
    const float* ue  = (const float*)d_in[3];
    const float* Wt  = (const float*)d_in[4];
    const float* bt  = (const float*)d_in[5];
    const float* Wim = (const float*)d_in[6];
    const float* bim = (const float*)d_in[7];
    const float* Wst = (const float*)d_in[8];
    const float* bst = (const float*)d_in[9];
    const float* Wu1 = (const float*)d_in[10];
    const float* bu1 = (const float*)d_in[11];
    const float* Wu2 = (const float*)d_in[12];
    const float* bu2 = (const float*)d_in[13];
    const float* Wi1 = (const float*)d_in[14];
    const float* bi1 = (const float*)d_in[15];
    const float* Wi2 = (const float*)d_in[16];
    const float* bi2 = (const float*)d_in[17];
    const int*   e32 = (const int*)d_in[18];
    int E = in_sizes[18] / 2;
    float* out = (float*)d_out;

    static int inited = 0;
    static cudaStream_t s2, s3;
    static cudaEvent_t ev_fork, ev_g, ev_u, ev_sp, ev_hi;
    if (!inited) {
        cudaFuncSetAttribute(feat_gemm_mma, cudaFuncAttributeMaxDynamicSharedMemorySize, SM_TOTAL);
        cudaFuncSetAttribute(hidden_gemm_mma, cudaFuncAttributeMaxDynamicSharedMemorySize, SM_TOTAL_H);
        cudaStreamCreateWithFlags(&s2, cudaStreamNonBlocking);
        cudaStreamCreateWithFlags(&s3, cudaStreamNonBlocking);
        cudaEventCreateWithFlags(&ev_fork, cudaEventDisableTiming);
        cudaEventCreateWithFlags(&ev_g,    cudaEventDisableTiming);
        cudaEventCreateWithFlags(&ev_u,    cudaEventDisableTiming);
        cudaEventCreateWithFlags(&ev_sp,   cudaEventDisableTiming);
        cudaEventCreateWithFlags(&ev_hi,   cudaEventDisableTiming);
        inited = 1;
    }

    __nv_bfloat16* W1h;  cudaGetSymbolAddress((void**)&W1h, g_W1h);
    __nv_bfloat16* W1l;  cudaGetSymbolAddress((void**)&W1l, g_W1l);

    // fork for side streams
    cudaEventRecord(ev_fork, 0);
    cudaStreamWaitEvent(s2, ev_fork, 0);
    cudaStreamWaitEvent(s3, ev_fork, 0);

    // ---- default stream: feature GEMM chain (feat_gemm is 4th launch for ncu) ----
    convertB<<<(D3 * KTOT + 255) / 256, 256>>>(Wt, Wim, Wst);            // 1
    convertW1<<<(2 * 128 * 192 + 255) / 256, 256>>>(Wu1, Wi1);           // 2
    bias_kernel<<<1, 256>>>(bt, bim, bst);                               // 3
    feat_gemm_mma<<<(NI + 127) / 128, 256, SM_TOTAL>>>(xt, xi, xs);      // 4

    // ---- stream s3: users (independent of feat chain) ----
    user_copy<<<(NU * 48 + 255) / 256, 256, 0, s3>>>(ue);
    cudaEventRecord(ev_u, s3);

    // ---- stream s2: graph preprocessing ----
    detect_kernel<<<1, 256, 0, s2>>>(e32);
    zero_kernel<<<(NN + 255) / 256, 256, 0, s2>>>();
    deg_kernel<<<(E + 255) / 256, 256, 0, s2>>>(e32, E);
    rinv_kernel<<<(NN + 255) / 256, 256, 0, s2>>>();
    scan_kernel<<<1, 1024, 0, s2>>>();
    fill_kernel<<<(E + 255) / 256, 256, 0, s2>>>(e32, E);
    cudaEventRecord(ev_g, s2);

    // join: spmm needs graph + features + users
    cudaStreamWaitEvent(0, ev_g, 0);
    cudaStreamWaitEvent(0, ev_u, 0);

    // propagation (pass 2 also emits Sh/Sl); 16 threads/node
    spmm<<<NN / 16, 256>>>(0);
    spmm<<<NN / 16, 256>>>(1);
    cudaEventRecord(ev_sp, 0);

    // attention: users on default stream, items concurrently on s3
    cudaStreamWaitEvent(s3, ev_sp, 0);
    hidden_gemm_mma<<<(NU + 127) / 128, 256, SM_TOTAL_H>>>(W1h, W1l, bu1, 0, NU);
    hidden_gemm_mma<<<(NI + 127) / 128, 256, SM_TOTAL_H, s3>>>(W1h + 128 * 192, W1l + 128 * 192, bi1, NU, NI);
    cudaEventRecord(ev_hi, s3);
    cudaStreamWaitEvent(0, ev_hi, 0);

    combine_kernel<<<(NN + 7) / 8, 256>>>(Wu2, bu2, Wi2, bi2, out);
}

// round 16
// speedup vs baseline: 1.4690x; 1.0877x over previous
#include <cuda_runtime.h>
#include <cuda_fp16.h>
#include <cstdint>

// ---------------- problem constants ----------------
#define NU 60000
#define NI 30000
#define NN 90000          // NU + NI
#define D  64
#define D3 192            // 3*D
#define MAXE_DIR 1000000
#define KTOT 1408         // 768 + 512 + 128
#define BK   64           // K chunk
#define NCHUNK 22         // 1408 / 64

// ---------------- device scratch ----------------
__device__ __align__(16) float g_X0[NN * D3];
__device__ __align__(16) float g_X1[NN * D3];
__device__ __align__(16) float g_S [NN * D3];
__device__ __align__(16) float g_H [NN * 128];
__device__ __align__(16) __half g_Bh[D3 * KTOT];          // B weights, single fp16
__device__ __align__(16) __half g_Sh[(size_t)NN * D3];    // S hi
__device__ __align__(16) __half g_Sl[(size_t)NN * D3];    // S lo
__device__ __align__(16) __half g_W1h[2 * 128 * 192];     // [which][n][k], single fp16
__device__ float g_bsum[D3];
__device__ int   g_deg[NN];
__device__ float g_rinv[NN];
__device__ int   g_rowptr[NN + 1];
__device__ int   g_cnt[NN];
__device__ int   g_col[MAXE_DIR];
__device__ int   g_is64;

// ---------------- helpers ----------------
__device__ __forceinline__ uint32_t smem_u32(const void* p) {
    uint32_t a;
    asm("{ .reg .u64 t; cvta.to.shared.u64 t, %1; cvt.u32.u64 %0, t; }" : "=r"(a) : "l"(p));
    return a;
}
__device__ __forceinline__ void cp16(uint32_t saddr, const void* g) {
    asm volatile("cp.async.ca.shared.global [%0], [%1], 16;" :: "r"(saddr), "l"(g));
}
__device__ __forceinline__ void st_zero16(uint32_t saddr) {
    asm volatile("st.shared.v4.u32 [%0], {%1,%1,%1,%1};" :: "r"(saddr), "r"(0u));
}
__device__ __forceinline__ void ldm4(uint32_t* r, uint32_t addr) {
    asm volatile("ldmatrix.sync.aligned.m8n8.x4.shared.b16 {%0,%1,%2,%3}, [%4];"
                 : "=r"(r[0]), "=r"(r[1]), "=r"(r[2]), "=r"(r[3]) : "r"(addr));
}
__device__ __forceinline__ void mma16816(float* d, const uint32_t* a, uint32_t b0, uint32_t b1) {
    asm volatile("mma.sync.aligned.m16n8k16.row.col.f32.f16.f16.f32 "
                 "{%0,%1,%2,%3}, {%4,%5,%6,%7}, {%8,%9}, {%0,%1,%2,%3};"
                 : "+f"(d[0]), "+f"(d[1]), "+f"(d[2]), "+f"(d[3])
                 : "r"(a[0]), "r"(a[1]), "r"(a[2]), "r"(a[3]), "r"(b0), "r"(b1));
}
__device__ __forceinline__ void split_f16(float v, __half& h, __half& l) {
    h = __float2half_rn(v);
    l = __float2half_rn(v - __half2float(h));
}

// ---------------- edge dtype detection (parallel) ----------------
__global__ void detect_kernel(const int* __restrict__ e32) {
    __shared__ int nz;
    if (threadIdx.x == 0) nz = 0;
    __syncthreads();
    int found = 0;
    for (int i = 1 + 2 * threadIdx.x; i < 2001; i += 512)
        if (e32[i] != 0) found = 1;
    if (found) nz = 1;
    __syncthreads();
    if (threadIdx.x == 0) g_is64 = (nz == 0);
}
__device__ __forceinline__ int edge_at(const int* __restrict__ e32, int idx) {
    int v = g_is64 ? e32[2 * idx] : e32[idx];
    return (v < 0) ? 0 : (v >= NN ? NN - 1 : v);
}

// ---------------- graph preprocessing ----------------
__global__ void zero_kernel() {
    int i = blockIdx.x * blockDim.x + threadIdx.x;
    if (i < NN) { g_deg[i] = 0; g_cnt[i] = 0; }
}
__global__ void deg_kernel(const int* __restrict__ e32, int E) {
    int i = blockIdx.x * blockDim.x + threadIdx.x;
    if (i < E) {
        atomicAdd(&g_deg[edge_at(e32, i)], 1);
        atomicAdd(&g_deg[edge_at(e32, E + i)], 1);
    }
}
__global__ void rinv_kernel() {
    int i = blockIdx.x * blockDim.x + threadIdx.x;
    if (i < NN) {
        int d = g_deg[i];
        g_rinv[i] = rsqrtf((float)(d < 1 ? 1 : d));
    }
}
__global__ void scan_kernel() {
    __shared__ int sums[1024];
    int t = threadIdx.x;
    const int CH = 88;
    int start = t * CH;
    int s = 0;
    for (int i = 0; i < CH; i++) {
        int idx = start + i;
        if (idx < NN) s += g_deg[idx];
    }
    sums[t] = s;
    __syncthreads();
    for (int off = 1; off < 1024; off <<= 1) {
        int add = (t >= off) ? sums[t - off] : 0;
        __syncthreads();
        sums[t] += add;
        __syncthreads();
    }
    int run = (t == 0) ? 0 : sums[t - 1];
    for (int i = 0; i < CH; i++) {
        int idx = start + i;
        if (idx < NN) { g_rowptr[idx] = run; run += g_deg[idx]; }
    }
    if (t == 1023) g_rowptr[NN] = sums[1023];
}
__global__ void fill_kernel(const int* __restrict__ e32, int E) {
    int i = blockIdx.x * blockDim.x + threadIdx.x;
    if (i < E) {
        int s = edge_at(e32, i);
        int d = edge_at(e32, E + i);
        int p0 = g_rowptr[s] + atomicAdd(&g_cnt[s], 1);
        g_col[p0] = d;
        int p1 = g_rowptr[d] + atomicAdd(&g_cnt[d], 1);
        g_col[p1] = s;
    }
}

// ---------------- weight conversions (small, one-shot) ----------------
__global__ void convertB(const float* __restrict__ Wt, const float* __restrict__ Wim,
                         const float* __restrict__ Wst) {
    int idx = blockIdx.x * blockDim.x + threadIdx.x;
    if (idx >= D3 * KTOT) return;
    int n = idx / KTOT, k = idx - n * KTOT;
    int b = n >> 6, d = n & 63;
    float v;
    if (k < 768)        v = Wt [((size_t)b * 768 + k) * 64 + d];
    else if (k < 1280)  v = Wim[((size_t)b * 512 + (k - 768)) * 64 + d];
    else                v = Wst[((size_t)b * 128 + (k - 1280)) * 64 + d];
    g_Bh[idx] = __float2half_rn(v);
}
__global__ void convertW1(const float* __restrict__ Wu1, const float* __restrict__ Wi1) {
    int idx = blockIdx.x * blockDim.x + threadIdx.x;
    if (idx >= 2 * 128 * 192) return;
    int which = idx / (128 * 192);
    int r = idx - which * (128 * 192);
    int n = r / 192, k = r - n * 192;
    const float* W = which ? Wi1 : Wu1;
    g_W1h[idx] = __float2half_rn(W[(size_t)k * 128 + n]);
}
__global__ void bias_kernel(const float* __restrict__ bt, const float* __restrict__ bim,
                            const float* __restrict__ bst) {
    int i = threadIdx.x;
    if (i < D3) g_bsum[i] = bt[i] + bim[i] + bst[i];
}

// ---------------- HMMA feat GEMM (fp16 2-product): X0_item = A@B^T + b -------
// smem: fp32 A double (64K), A fp16 hi/lo single (32K), B fp16 double (48K) = 144K
#define FAF0 0
#define FAF1 32768
#define FAH  65536
#define FAL  81920
#define FB0  98304
#define FB1  122880
#define SM_TOTAL 147456     // 144 KB

__device__ __forceinline__ void feat_issue(uint32_t sb, int stage, int mi0, int c, int tid,
                                           const float* xt, const float* xi, const float* xs) {
    const float* Ap; int stride, off;
    if (c < 12)      { Ap = xt; stride = 768; off = c * 64; }
    else if (c < 20) { Ap = xi; stride = 512; off = c * 64 - 768; }
    else             { Ap = xs; stride = 128; off = c * 64 - 1280; }
    uint32_t abase = sb + (stage ? FAF1 : FAF0);
    for (int li = tid; li < 2048; li += 256) {
        int row = li >> 4, j = li & 15;
        int gr = mi0 + row;
        uint32_t dst = abase + row * 256 + j * 16;
        if (gr < NI) cp16(dst, Ap + (size_t)gr * stride + off + j * 4);
        else         st_zero16(dst);
    }
    uint32_t bbase = sb + (stage ? FB1 : FB0);
    int k0 = c * BK;
    for (int li = tid; li < 1536; li += 256) {
        int row = li >> 3, seg = li & 7;
        size_t o = (size_t)row * KTOT + k0 + seg * 8;
        uint32_t sw = row * 128 + ((seg * 16) ^ ((row & 7) << 4));
        cp16(bbase + sw, g_Bh + o);
    }
}

__global__ void __launch_bounds__(256, 1)
feat_gemm_mma(const float* __restrict__ xt, const float* __restrict__ xi,
              const float* __restrict__ xs) {
    extern __shared__ char smem[];
    uint32_t sb = smem_u32(smem);
    int tid = threadIdx.x;
    int wid = tid >> 5, lane = tid & 31;
    int wm = wid & 3, wn = wid >> 2;
    int mi0 = blockIdx.x * 128;

    float acc[2][12][4];
    #pragma unroll
    for (int i = 0; i < 2; i++)
        #pragma unroll
        for (int j = 0; j < 12; j++)
            #pragma unroll
            for (int q = 0; q < 4; q++) acc[i][j][q] = 0.f;

    feat_issue(sb, 0, mi0, 0, tid, xt, xi, xs);
    asm volatile("cp.async.commit_group;" ::: "memory");

    for (int c = 0; c < NCHUNK; c++) {
        if (c + 1 < NCHUNK) {
            feat_issue(sb, (c + 1) & 1, mi0, c + 1, tid, xt, xi, xs);
            asm volatile("cp.async.commit_group;" ::: "memory");
            asm volatile("cp.async.wait_group 1;" ::: "memory");
        } else {
            asm volatile("cp.async.wait_group 0;" ::: "memory");
        }
        __syncthreads();

        // convert fp32 A -> swizzled fp16 hi/lo (single buffer)
        {
            uint32_t abase = sb + ((c & 1) ? FAF1 : FAF0);
            const char* sp = smem + (abase - sb);
            for (int li = tid; li < 1024; li += 256) {
                int row = li >> 3, seg = li & 7;
                const float4* f4 = (const float4*)(sp + row * 256 + seg * 32);
                float4 v0 = f4[0], v1 = f4[1];
                __half h[8], l[8];
                split_f16(v0.x, h[0], l[0]); split_f16(v0.y, h[1], l[1]);
                split_f16(v0.z, h[2], l[2]); split_f16(v0.w, h[3], l[3]);
                split_f16(v1.x, h[4], l[4]); split_f16(v1.y, h[5], l[5]);
                split_f16(v1.z, h[6], l[6]); split_f16(v1.w, h[7], l[7]);
                uint32_t sw = row * 128 + ((seg * 16) ^ ((row & 7) << 4));
                *(uint4*)(smem + (FAH + sw)) = *(const uint4*)h;
                *(uint4*)(smem + (FAL + sw)) = *(const uint4*)l;
            }
        }
        __syncthreads();

        uint32_t bbase = sb + ((c & 1) ? FB1 : FB0);
        #pragma unroll
        for (int k16 = 0; k16 < 4; k16++) {
            uint32_t ah[2][4], al[2][4];
            #pragma unroll
            for (int mi = 0; mi < 2; mi++) {
                int r = wm * 32 + mi * 16 + (lane & 15);
                int kb = k16 * 32 + ((lane >> 4) << 4);
                uint32_t off = r * 128 + (kb ^ ((r & 7) << 4));
                ldm4(ah[mi], sb + FAH + off);
                ldm4(al[mi], sb + FAL + off);
            }
            #pragma unroll
            for (int nn = 0; nn < 6; nn++) {
                int g = lane >> 3;
                int r = wn * 96 + nn * 16 + ((g & 2) << 2) + (lane & 7);
                int kb = k16 * 32 + ((g & 1) << 4);
                uint32_t off = r * 128 + (kb ^ ((r & 7) << 4));
                uint32_t bh[4];
                ldm4(bh, bbase + off);
                #pragma unroll
                for (int mi = 0; mi < 2; mi++) {
                    mma16816(acc[mi][nn * 2 + 0], ah[mi], bh[0], bh[1]);
                    mma16816(acc[mi][nn * 2 + 1], ah[mi], bh[2], bh[3]);
                    mma16816(acc[mi][nn * 2 + 0], al[mi], bh[0], bh[1]);
                    mma16816(acc[mi][nn * 2 + 1], al[mi], bh[2], bh[3]);
                }
            }
        }
        __syncthreads();
    }

    #pragma unroll
    for (int mi = 0; mi < 2; mi++) {
        #pragma unroll
        for (int nn = 0; nn < 6; nn++) {
            #pragma unroll
            for (int nf = 0; nf < 2; nf++) {
                float* f = acc[mi][nn * 2 + nf];
                int row = mi0 + wm * 32 + mi * 16 + (lane >> 2);
                int col = wn * 96 + nn * 16 + nf * 8 + (lane & 3) * 2;
                #pragma unroll
                for (int h = 0; h < 2; h++) {
                    int rr = row + h * 8;
                    if (rr < NI) {
                        size_t o = (size_t)(NU + rr) * D3 + col;
                        float v0 = f[h * 2 + 0] + g_bsum[col];
                        float v1 = f[h * 2 + 1] + g_bsum[col + 1];
                        g_X0[o] = v0;     g_X0[o + 1] = v1;
                        g_S [o] = v0;     g_S [o + 1] = v1;
                    }
                }
            }
        }
    }
}

// ---------------- users ----------------
__global__ void user_copy(const float* __restrict__ ue) {
    int idx = blockIdx.x * blockDim.x + threadIdx.x;
    if (idx >= NU * 48) return;
    int n = idx / 48;
    int q = idx - n * 48;
    int b = q >> 4;
    int d4 = q & 15;
    float4 v = ((const float4*)ue)[((size_t)b * NU + n) * 16 + d4];
    ((float4*)g_X0)[(size_t)n * 48 + q] = v;
    ((float4*)g_S )[(size_t)n * 48 + q] = v;
}

// ---------------- SpMM: 16 threads/node, 3 float4 each ----------------
__global__ void spmm(int pass) {
    const float4* __restrict__ Xin4  = (const float4*)(pass ? g_X1 : g_X0);
    float4*       __restrict__ Xout4 = (float4*)(pass ? g_X0 : g_X1);
    int node = blockIdx.x * 16 + (threadIdx.x >> 4);
    int t = threadIdx.x & 15;
    int e0 = g_rowptr[node], e1 = g_rowptr[node + 1];
    float4 A0 = make_float4(0.f, 0.f, 0.f, 0.f), A1 = A0, A2 = A0;
    for (int e = e0; e < e1; e++) {
        int d = g_col[e];
        float w = g_rinv[d];
        const float4* xr = Xin4 + (size_t)d * 48;
        float4 v0 = xr[t], v1 = xr[t + 16], v2 = xr[t + 32];
        A0.x += w * v0.x; A0.y += w * v0.y; A0.z += w * v0.z; A0.w += w * v0.w;
        A1.x += w * v1.x; A1.y += w * v1.y; A1.z += w * v1.z; A1.w += w * v1.w;
        A2.x += w * v2.x; A2.y += w * v2.y; A2.z += w * v2.z; A2.w += w * v2.w;
    }
    float rs = g_rinv[node];
    A0.x *= rs; A0.y *= rs; A0.z *= rs; A0.w *= rs;
    A1.x *= rs; A1.y *= rs; A1.z *= rs; A1.w *= rs;
    A2.x *= rs; A2.y *= rs; A2.z *= rs; A2.w *= rs;
    size_t o = (size_t)node * 48 + t;
    Xout4[o] = A0;  Xout4[o + 16] = A1;  Xout4[o + 32] = A2;
    float4* Sf4 = (float4*)g_S;
    float4 s0 = Sf4[o], s1 = Sf4[o + 16], s2 = Sf4[o + 32];
    s0.x += A0.x; s0.y += A0.y; s0.z += A0.z; s0.w += A0.w;
    s1.x += A1.x; s1.y += A1.y; s1.z += A1.z; s1.w += A1.w;
    s2.x += A2.x; s2.y += A2.y; s2.z += A2.z; s2.w += A2.w;
    Sf4[o] = s0;  Sf4[o + 16] = s1;  Sf4[o + 32] = s2;
    if (pass) {
        float4 ss[3] = {s0, s1, s2};
        #pragma unroll
        for (int q = 0; q < 3; q++) {
            __half h0, l0, h1, l1, h2, l2, h3, l3;
            split_f16(ss[q].x, h0, l0); split_f16(ss[q].y, h1, l1);
            split_f16(ss[q].z, h2, l2); split_f16(ss[q].w, h3, l3);
            size_t bo = (size_t)node * D3 + 4 * t + 64 * q;
            *(__half2*)(g_Sh + bo)     = __halves2half2(h0, h1);
            *(__half2*)(g_Sh + bo + 2) = __halves2half2(h2, h3);
            *(__half2*)(g_Sl + bo)     = __halves2half2(l0, l1);
            *(__half2*)(g_Sl + bo + 2) = __halves2half2(l2, l3);
        }
    }
}

// ---------------- HMMA attention hidden GEMM (fp16 2-product) ----------------
#define HS_SH 0
#define HS_SL 16384
#define HS_WH 32768
#define HSTAGE_SZ 49152
#define SM_TOTAL_H (2 * HSTAGE_SZ)

__device__ __forceinline__ void issue_loads_h(uint32_t sb, int stage, int m0, int c, int tid,
                                              int row_base, int nrows,
                                              const __half* Wh) {
    uint32_t base = sb + stage * HSTAGE_SZ;
    int k0 = c * 64;
    for (int li = tid; li < 1024; li += 256) {
        int row = li >> 3, seg = li & 7;
        uint32_t sw = row * 128 + ((seg * 16) ^ ((row & 7) << 4));
        if (m0 + row < nrows) {
            size_t o = (size_t)(row_base + m0 + row) * D3 + k0 + seg * 8;
            cp16(base + HS_SH + sw, g_Sh + o);
            cp16(base + HS_SL + sw, g_Sl + o);
        } else {
            st_zero16(base + HS_SH + sw);
            st_zero16(base + HS_SL + sw);
        }
    }
    for (int li = tid; li < 1024; li += 256) {
        int row = li >> 3, seg = li & 7;
        size_t o = (size_t)row * D3 + k0 + seg * 8;
        uint32_t sw = row * 128 + ((seg * 16) ^ ((row & 7) << 4));
        cp16(base + HS_WH + sw, Wh + o);
    }
}

__global__ void __launch_bounds__(256, 1)
hidden_gemm_mma(const __half* __restrict__ Wh,
                const float* __restrict__ b1, int row_base, int nrows)
{
    extern __shared__ char smem[];
    uint32_t sb = smem_u32(smem);
    int tid = threadIdx.x;
    int wid = tid >> 5, lane = tid & 31;
    int wm = wid & 3, wn = wid >> 2;
    int m0 = blockIdx.x * 128;

    float acc[2][8][4];
    #pragma unroll
    for (int i = 0; i < 2; i++)
        #pragma unroll
        for (int j = 0; j < 8; j++)
            #pragma unroll
            for (int q = 0; q < 4; q++) acc[i][j][q] = 0.f;

    issue_loads_h(sb, 0, m0, 0, tid, row_base, nrows, Wh);
    asm volatile("cp.async.commit_group;" ::: "memory");

    for (int c = 0; c < 3; c++) {
        if (c + 1 < 3) {
            issue_loads_h(sb, (c + 1) & 1, m0, c + 1, tid, row_base, nrows, Wh);
            asm volatile("cp.async.commit_group;" ::: "memory");
            asm volatile("cp.async.wait_group 1;" ::: "memory");
        } else {
            asm volatile("cp.async.wait_group 0;" ::: "memory");
        }
        __syncthreads();

        uint32_t base = sb + (c & 1) * HSTAGE_SZ;
        #pragma unroll
        for (int k16 = 0; k16 < 4; k16++) {
            uint32_t ah[2][4], al[2][4];
            #pragma unroll
            for (int mi = 0; mi < 2; mi++) {
                int r = wm * 32 + mi * 16 + (lane & 15);
                int kb = k16 * 32 + ((lane >> 4) << 4);
                uint32_t off = r * 128 + (kb ^ ((r & 7) << 4));
                ldm4(ah[mi], base + HS_SH + off);
                ldm4(al[mi], base + HS_SL + off);
            }
            #pragma unroll
            for (int nn = 0; nn < 4; nn++) {
                int g = lane >> 3;
                int r = wn * 64 + nn * 16 + ((g & 2) << 2) + (lane & 7);
                int kb = k16 * 32 + ((g & 1) << 4);
                uint32_t off = r * 128 + (kb ^ ((r & 7) << 4));
                uint32_t bh[4];
                ldm4(bh, base + HS_WH + off);
                #pragma unroll
                for (int mi = 0; mi < 2; mi++) {
                    mma16816(acc[mi][nn * 2 + 0], ah[mi], bh[0], bh[1]);
                    mma16816(acc[mi][nn * 2 + 1], ah[mi], bh[2], bh[3]);
                    mma16816(acc[mi][nn * 2 + 0], al[mi], bh[0], bh[1]);
                    mma16816(acc[mi][nn * 2 + 1], al[mi], bh[2], bh[3]);
                }
            }
        }
        __syncthreads();
    }

    const float alpha = 1.f / 3.f;
    #pragma unroll
    for (int mi = 0; mi < 2; mi++) {
        #pragma unroll
        for (int nn = 0; nn < 4; nn++) {
            #pragma unroll
            for (int nf = 0; nf < 2; nf++) {
                float* f = acc[mi][nn * 2 + nf];
                int row = m0 + wm * 32 + mi * 16 + (lane >> 2);
                int col = wn * 64 + nn * 16 + nf * 8 + (lane & 3) * 2;
                #pragma unroll
                for (int h = 0; h < 2; h++) {
                    int rr = row + h * 8;
                    if (rr < nrows) {
                        size_t o = (size_t)(row_base + rr) * 128 + col;
                        g_H[o]     = fmaxf(alpha * f[h * 2 + 0] + b1[col], 0.f);
                        g_H[o + 1] = fmaxf(alpha * f[h * 2 + 1] + b1[col + 1], 0.f);
                    }
                }
            }
        }
    }
}

// ---------------- logits + softmax + combine ----------------
__global__ void combine_kernel(const float* __restrict__ Wu2, const float* __restrict__ bu2,
                               const float* __restrict__ Wi2, const float* __restrict__ bi2,
                               float* __restrict__ out)
{
    __shared__ float W2s[2][384];
    int tid = threadIdx.x;
    for (int li = tid; li < 384; li += 256) {
        W2s[0][li] = Wu2[li];
        W2s[1][li] = Wi2[li];
    }
    __syncthreads();
    int warp = tid >> 5, lane = tid & 31;
    int n = blockIdx.x * 8 + warp;
    if (n >= NN) return;
    int sel = (n >= NU) ? 1 : 0;
    const float* b2 = sel ? bi2 : bu2;

    float p0 = 0.f, p1 = 0.f, p2 = 0.f;
    #pragma unroll
    for (int q = 0; q < 4; q++) {
        int j = lane + 32 * q;
        float h = g_H[(size_t)n * 128 + j];
        p0 += h * W2s[sel][j * 3 + 0];
        p1 += h * W2s[sel][j * 3 + 1];
        p2 += h * W2s[sel][j * 3 + 2];
    }
    #pragma unroll
    for (int off = 16; off; off >>= 1) {
        p0 += __shfl_xor_sync(0xffffffff, p0, off);
        p1 += __shfl_xor_sync(0xffffffff, p1, off);
        p2 += __shfl_xor_sync(0xffffffff, p2, off);
    }
    float l0 = p0 + b2[0], l1 = p1 + b2[1], l2 = p2 + b2[2];
    float mx = fmaxf(l0, fmaxf(l1, l2));
    float e0 = __expf(l0 - mx), e1 = __expf(l1 - mx), e2 = __expf(l2 - mx);
    float inv = 1.f / (e0 + e1 + e2);
    float a0 = e0 * inv, a1 = e1 * inv, a2 = e2 * inv;
    const float sc = 1.f / 3.f;
    #pragma unroll
    for (int q = 0; q < 2; q++) {
        int d = lane + 32 * q;
        float u0 = g_S[(size_t)n * D3 + d] * sc;
        float u1 = g_S[(size_t)n * D3 + 64 + d] * sc;
        float u2 = g_S[(size_t)n * D3 + 128 + d] * sc;
        out[(size_t)n * D + d] = a0 * u0 + a1 * u1 + a2 * u2;
    }
}

// ---------------- launch ----------------
extern "C" void kernel_launch(void* const* d_in, const int* in_sizes, int n_in,
                              void* d_out, int out_size)
{
    const float* xt  = (const float*)d_in[0];
    const float* xi  = (const float*)d_in[1];
    const float* xs  = (const float*)d_in[2];
    const float* ue  = (const float*)d_in[3];
    const float* Wt  = (const float*)d_in[4];
    const float* bt  = (const float*)d_in[5];
    const float* Wim = (const float*)d_in[6];
    const float* bim = (const float*)d_in[7];
    const float* Wst = (const float*)d_in[8];
    const float* bst = (const float*)d_in[9];
    const float* Wu1 = (const float*)d_in[10];
    const float* bu1 = (const float*)d_in[11];
    const float* Wu2 = (const float*)d_in[12];
    const float* bu2 = (const float*)d_in[13];
    const float* Wi1 = (const float*)d_in[14];
    const float* bi1 = (const float*)d_in[15];
    const float* Wi2 = (const float*)d_in[16];
    const float* bi2 = (const float*)d_in[17];
    const int*   e32 = (const int*)d_in[18];
    int E = in_sizes[18] / 2;
    float* out = (float*)d_out;

    static int inited = 0;
    static cudaStream_t s2, s3;
    static cudaEvent_t ev_fork, ev_g, ev_u, ev_sp, ev_hi;
    if (!inited) {
        cudaFuncSetAttribute(feat_gemm_mma, cudaFuncAttributeMaxDynamicSharedMemorySize, SM_TOTAL);
        cudaFuncSetAttribute(hidden_gemm_mma, cudaFuncAttributeMaxDynamicSharedMemorySize, SM_TOTAL_H);
        cudaStreamCreateWithFlags(&s2, cudaStreamNonBlocking);
        cudaStreamCreateWithFlags(&s3, cudaStreamNonBlocking);
        cudaEventCreateWithFlags(&ev_fork, cudaEventDisableTiming);
        cudaEventCreateWithFlags(&ev_g,    cudaEventDisableTiming);
        cudaEventCreateWithFlags(&ev_u,    cudaEventDisableTiming);
        cudaEventCreateWithFlags(&ev_sp,   cudaEventDisableTiming);
        cudaEventCreateWithFlags(&ev_hi,   cudaEventDisableTiming);
        inited = 1;
    }

    __half* W1h;  cudaGetSymbolAddress((void**)&W1h, g_W1h);

    // fork for side streams
    cudaEventRecord(ev_fork, 0);
    cudaStreamWaitEvent(s2, ev_fork, 0);
    cudaStreamWaitEvent(s3, ev_fork, 0);

    // ---- default stream: feature GEMM chain (feat_gemm is 4th launch for ncu) ----
    convertB<<<(D3 * KTOT + 255) / 256, 256>>>(Wt, Wim, Wst);            // 1
    convertW1<<<(2 * 128 * 192 + 255) / 256, 256>>>(Wu1, Wi1);           // 2
    bias_kernel<<<1, 256>>>(bt, bim, bst);                               // 3
    feat_gemm_mma<<<(NI + 127) / 128, 256, SM_TOTAL>>>(xt, xi, xs);      // 4

    // ---- stream s3: users (independent of feat chain) ----
    user_copy<<<(NU * 48 + 255) / 256, 256, 0, s3>>>(ue);
    cudaEventRecord(ev_u, s3);

    // ---- stream s2: graph preprocessing ----
    detect_kernel<<<1, 256, 0, s2>>>(e32);
    zero_kernel<<<(NN + 255) / 256, 256, 0, s2>>>();
    deg_kernel<<<(E + 255) / 256, 256, 0, s2>>>(e32, E);
    rinv_kernel<<<(NN + 255) / 256, 256, 0, s2>>>();
    scan_kernel<<<1, 1024, 0, s2>>>();
    fill_kernel<<<(E + 255) / 256, 256, 0, s2>>>(e32, E);
    cudaEventRecord(ev_g, s2);

    // join: spmm needs graph + features + users
    cudaStreamWaitEvent(0, ev_g, 0);
    cudaStreamWaitEvent(0, ev_u, 0);

    // propagation (pass 2 also emits Sh/Sl); 16 threads/node
    spmm<<<NN / 16, 256>>>(0);
    spmm<<<NN / 16, 256>>>(1);
    cudaEventRecord(ev_sp, 0);

    // attention: users on default stream, items concurrently on s3
    cudaStreamWaitEvent(s3, ev_sp, 0);
    hidden_gemm_mma<<<(NU + 127) / 128, 256, SM_TOTAL_H>>>(W1h, bu1, 0, NU);
    hidden_gemm_mma<<<(NI + 127) / 128, 256, SM_TOTAL_H, s3>>>(W1h + 128 * 192, bi1, NU, NI);
    cudaEventRecord(ev_hi, s3);
    cudaStreamWaitEvent(0, ev_hi, 0);

    combine_kernel<<<(NN + 7) / 8, 256>>>(Wu2, bu2, Wi2, bi2, out);
}